// round 17
// baseline (speedup 1.0000x reference)
#include <cuda_runtime.h>
#include <cuda_bf16.h>
#include <cstdint>

#define HW   (128*128)        // 16384 pixels per (b,c) plane
#define CHW  (64*HW)          // one batch image, 64 channels
#define NPIX (4*HW)           // total pixels across batch

// Scratch tensors (allocation-free rule: __device__ globals)
__device__ float g_Q[4*CHW];
__device__ float g_V[4*CHW];
__device__ float g_O[4*CHW];

// ---------------------------------------------------------------------------
// bf16 tensor-core helpers (legacy mma.sync m16n8k16 — PTX sm_80+)
// ---------------------------------------------------------------------------
__device__ __forceinline__ uint32_t pack_bf16(float lo, float hi) {
    __nv_bfloat16 a = __float2bfloat16(lo);
    __nv_bfloat16 b = __float2bfloat16(hi);
    uint16_t ua = *(uint16_t*)&a, ub = *(uint16_t*)&b;
    return (uint32_t)ua | ((uint32_t)ub << 16);
}
__device__ __forceinline__ float bf16_hi_part(float v, float& rem) {
    __nv_bfloat16 h = __float2bfloat16(v);
    float hf = __bfloat162float(h);
    rem = v - hf;
    return hf;
}

__device__ __forceinline__ void mma_bf16(float* d,
                                         uint32_t a0, uint32_t a1,
                                         uint32_t a2, uint32_t a3,
                                         uint32_t b0, uint32_t b1) {
    asm volatile(
        "mma.sync.aligned.m16n8k16.row.col.f32.bf16.bf16.f32 "
        "{%0,%1,%2,%3}, {%4,%5,%6,%7}, {%8,%9}, {%0,%1,%2,%3};\n"
        : "+f"(d[0]), "+f"(d[1]), "+f"(d[2]), "+f"(d[3])
        : "r"(a0), "r"(a1), "r"(a2), "r"(a3), "r"(b0), "r"(b1));
}

// ---------------------------------------------------------------------------
// Persistent conv1x1 via bf16 m16n8k16, 3-pass split, 4 tiles per CTA,
// double-buffered A with register prefetch (R15, measured-good).
// ---------------------------------------------------------------------------
#define AH_STR 42
#define ABUF_W (128*AH_STR)          // 5376 words per array
#define DS_STR 132
#define TILES  4
#define NCTA   128                   // CTAs per conv job
#define CONV_SMEM ((2*2*ABUF_W + 4096 + 64) * 4)   // 102656 B

__device__ __forceinline__ void conv_mma_persistent(
    const float* __restrict__ in, const float* __restrict__ w,
    const float* __restrict__ bias, const float* __restrict__ resid,
    float* __restrict__ out)
{
    extern __shared__ float sm[];
    uint32_t* smw = (uint32_t*)sm;
    uint2* BfH = (uint2*)(smw + 4*ABUF_W);
    uint2* BfL = (uint2*)(smw + 4*ABUF_W + 2048);
    float* bs  = sm + 4*ABUF_W + 4096;

    int tid = threadIdx.x;

    // ---- pre-split B into bf16 fragment layout (ONCE per CTA) ----
    #pragma unroll
    for (int e = tid; e < 1024; e += 256) {
        int combo = e >> 5, ln = e & 31;
        int kb = combo >> 3, nb = combo & 7;
        int g = ln >> 2, t = ln & 3;
        const float* wf = w + (nb*8 + g)*64 + kb*16 + 2*t;
        float r0, r1, r2, r3;
        float h0 = bf16_hi_part(wf[0], r0);
        float h1 = bf16_hi_part(wf[1], r1);
        float h2 = bf16_hi_part(wf[8], r2);
        float h3 = bf16_hi_part(wf[9], r3);
        BfH[e] = make_uint2(pack_bf16(h0, h1), pack_bf16(h2, h3));
        BfL[e] = make_uint2(pack_bf16(r0, r1), pack_bf16(r2, r3));
    }
    if (tid < 64) bs[tid] = bias[tid];

    int px  = tid & 127;
    int pcb = tid >> 7;

    // ---- load tile 0 into buffer 0 ----
    {
        int pix0 = blockIdx.x * 128;
        int b = pix0 >> 14, p = pix0 & (HW - 1);
        const float* inp = in + (size_t)b*CHW + p;
        uint32_t* Ah = smw;
        uint32_t* Al = smw + ABUF_W;
        #pragma unroll
        for (int j = 0; j < 16; j++) {
            int pc = pcb + 2*j;
            float v0 = inp[(2*pc)*HW + px];
            float v1 = inp[(2*pc + 1)*HW + px];
            float r0, r1;
            float h0 = bf16_hi_part(v0, r0);
            float h1 = bf16_hi_part(v1, r1);
            int cc = pc & 7;
            int col = (pc & ~7) | (((cc & 3) << 1) | (cc >> 2));
            Ah[px*AH_STR + col] = pack_bf16(h0, h1);
            Al[px*AH_STR + col] = pack_bf16(r0, r1);
        }
    }
    __syncthreads();

    int wp   = tid >> 5;
    int lane = tid & 31;
    int g    = lane >> 2;
    int t4   = lane & 3;

    int cur = 0;
    #pragma unroll 1
    for (int t = 0; t < TILES; t++) {
        int pix0 = (blockIdx.x + NCTA*t) * 128;
        int b = pix0 >> 14, p = pix0 & (HW - 1);

        // ---- issue prefetch LDGs for next tile ----
        float av0[16], av1[16];
        if (t < TILES-1) {
            int pix2 = (blockIdx.x + NCTA*(t+1)) * 128;
            int b2 = pix2 >> 14, p2 = pix2 & (HW - 1);
            const float* inp2 = in + (size_t)b2*CHW + p2;
            #pragma unroll
            for (int j = 0; j < 16; j++) {
                int pc = pcb + 2*j;
                av0[j] = inp2[(2*pc)*HW + px];
                av1[j] = inp2[(2*pc + 1)*HW + px];
            }
        }

        // ---- mma mainloop on buf[cur] ----
        uint32_t* Ah = smw + cur*2*ABUF_W;
        uint32_t* Al = Ah + ABUF_W;

        float acc[8][4];
        #pragma unroll
        for (int nb = 0; nb < 8; nb++)
            #pragma unroll
            for (int j = 0; j < 4; j++) acc[nb][j] = 0.f;

        const uint32_t* ahp = Ah + (16*wp + g)*AH_STR + 2*t4;
        const uint32_t* alp = Al + (16*wp + g)*AH_STR + 2*t4;

        #pragma unroll
        for (int kb = 0; kb < 4; kb++) {
            uint2 rgh  = *(const uint2*)(ahp + kb*8);
            uint2 rg8h = *(const uint2*)(ahp + 8*AH_STR + kb*8);
            uint2 rgl  = *(const uint2*)(alp + kb*8);
            uint2 rg8l = *(const uint2*)(alp + 8*AH_STR + kb*8);

            const uint2* bh = BfH + kb*8*32 + lane;
            const uint2* bl = BfL + kb*8*32 + lane;
            #pragma unroll
            for (int nb = 0; nb < 8; nb++) {
                uint2 h = bh[nb*32];
                uint2 l = bl[nb*32];
                mma_bf16(acc[nb], rgh.x, rg8h.x, rgh.y, rg8h.y, h.x, h.y);
                mma_bf16(acc[nb], rgl.x, rg8l.x, rgl.y, rg8l.y, h.x, h.y);
                mma_bf16(acc[nb], rgh.x, rg8h.x, rgh.y, rg8h.y, l.x, l.y);
            }
        }
        __syncthreads();

        // ---- convert+store prefetched A into the other buffer ----
        if (t < TILES-1) {
            uint32_t* Ah2 = smw + (cur^1)*2*ABUF_W;
            uint32_t* Al2 = Ah2 + ABUF_W;
            #pragma unroll
            for (int j = 0; j < 16; j++) {
                int pc = pcb + 2*j;
                float r0, r1;
                float h0 = bf16_hi_part(av0[j], r0);
                float h1 = bf16_hi_part(av1[j], r1);
                int cc = pc & 7;
                int col = (pc & ~7) | (((cc & 3) << 1) | (cc >> 2));
                Ah2[px*AH_STR + col] = pack_bf16(h0, h1);
                Al2[px*AH_STR + col] = pack_bf16(r0, r1);
            }
        }

        // ---- epilogue via smem staging ----
        float* Ds = (float*)(smw + cur*2*ABUF_W);
        #pragma unroll
        for (int nb = 0; nb < 8; nb++) {
            int f0 = nb*8 + 2*t4;
            int r0 = 16*wp + g;
            Ds[f0*DS_STR + r0]         = acc[nb][0];
            Ds[(f0+1)*DS_STR + r0]     = acc[nb][1];
            Ds[f0*DS_STR + r0 + 8]     = acc[nb][2];
            Ds[(f0+1)*DS_STR + r0 + 8] = acc[nb][3];
        }
        __syncthreads();

        float* outp = out + (size_t)b*CHW + p;
        const float* rp = resid ? (resid + (size_t)b*CHW + p) : nullptr;
        #pragma unroll
        for (int r = 0; r < 8; r++) {
            int f = wp*8 + r;
            float4 v = *(const float4*)(Ds + f*DS_STR + lane*4);
            float bv = bs[f];
            v.x += bv; v.y += bv; v.z += bv; v.w += bv;
            if (rp) {
                float4 rv = *(const float4*)(rp + (size_t)f*HW + lane*4);
                v.x += rv.x; v.y += rv.y; v.z += rv.z; v.w += rv.w;
            }
            *(float4*)(outp + (size_t)f*HW + lane*4) = v;
        }
        __syncthreads();
        cur ^= 1;
    }
}

__global__ void __launch_bounds__(256, 2) qv_conv_kernel(
    const float* __restrict__ x,  const float* __restrict__ y,
    const float* __restrict__ wx, const float* __restrict__ bx,
    const float* __restrict__ wy, const float* __restrict__ by,
    float* __restrict__ Q, float* __restrict__ V)
{
    if (blockIdx.y == 0) conv_mma_persistent(y, wy, by, nullptr, Q);
    else                 conv_mma_persistent(x, wx, bx, nullptr, V);
}

__global__ void __launch_bounds__(256, 2) out_conv_kernel(
    const float* __restrict__ in, const float* __restrict__ w,
    const float* __restrict__ bias, const float* __restrict__ resid,
    float* __restrict__ out)
{
    conv_mma_persistent(in, w, bias, resid, out);
}

// ---------------------------------------------------------------------------
// Local attention (5x5 window, zero-padded) — channel-split warp spec.
// Tile: interior 16h x 32w (512 px), halo 20 x 36 = 720 positions.
// 512 threads = 256 pixel-pairs (2 vertical px each) x 2 channel-halves.
// Each thread: 2 px, 32 channels, 6x5 shared window -> 15 LDS/px/ch.
// Partial scores exchanged through smem; softmax replicated per half.
// smem: halo chunk [32][720] = 92160B @0, partials [2][256][50] = 102400B.
// ---------------------------------------------------------------------------
#define HT 16
#define WT 32
#define HR (HT + 4)     // 20
#define WC (WT + 4)     // 36
#define NPOS (HR * WC)  // 720
#define ACH 32          // channels per halo chunk
#define PART_OFF (ACH*NPOS)             // word offset of partial buf (23040)
#define ATTN_SMEM ((ACH*NPOS + 2*256*50) * 4)   // 194560 B

__device__ __forceinline__ void load_halo_chunk(
    const float* __restrict__ src,      // base: X + b*CHW + ck*ACH*HW
    float* __restrict__ s, int tid, int h0, int w0)
{
    #pragma unroll 5
    for (int i = tid; i < ACH*NPOS; i += 512) {
        int c   = i / NPOS;
        int pos = i - c*NPOS;
        int r   = pos / WC;
        int col = pos - r*WC;
        int gh  = h0 + r - 2;
        int gw  = w0 + col - 2;
        float v = 0.f;
        if ((unsigned)gh < 128u && (unsigned)gw < 128u)
            v = src[c*HW + gh*128 + gw];
        s[i] = v;
    }
}

__global__ void __launch_bounds__(512, 1) attn_kernel(
    const float* __restrict__ Q, const float* __restrict__ V,
    float* __restrict__ O)
{
    extern __shared__ float s[];

    int tid  = threadIdx.x;
    int pidx = tid & 255;          // pixel-pair index
    int wx   = pidx & 31;          // column within tile
    int hy   = pidx >> 5;          // row pair: rows 2hy, 2hy+1 (0..7 -> 16 rows)
    int half = tid >> 8;           // channel half 0/1
    int b    = blockIdx.z;
    int h0   = blockIdx.y * HT;
    int w0   = blockIdx.x * WT;

    int r0 = hy*2;
    float A1[25], A2[25];
    #pragma unroll
    for (int k = 0; k < 25; k++) { A1[k] = 0.f; A2[k] = 0.f; }

    // ---- partial scores: 2 chunks x 16 own channels ----
    const float* Qb = Q + (size_t)b*CHW;
    #pragma unroll
    for (int ck = 0; ck < 2; ck++) {
        load_halo_chunk(Qb + ck*ACH*HW, s, tid, h0, w0);
        __syncthreads();

        const float* base0 = s + (half*16)*NPOS + r0*WC + wx;
        for (int c = 0; c < 16; c++) {
            const float* qs = base0 + c*NPOS;
            float n[6][5];
            #pragma unroll
            for (int j = 0; j < 6; j++)
                #pragma unroll
                for (int i = 0; i < 5; i++)
                    n[j][i] = qs[j*WC + i];
            float q1 = n[2][2];
            float q2 = n[3][2];
            #pragma unroll
            for (int j = 0; j < 5; j++)
                #pragma unroll
                for (int i = 0; i < 5; i++) {
                    A1[j*5+i] += q1 * n[j][i];
                    A2[j*5+i] += q2 * n[j+1][i];
                }
        }
        __syncthreads();
    }

    // ---- exchange partials: each half writes its 50, reads other half's ----
    float* part = s + PART_OFF;
    {
        float* mine = part + (half*256 + pidx)*50;
        #pragma unroll
        for (int k = 0; k < 25; k++) { mine[k] = A1[k]; mine[25+k] = A2[k]; }
    }
    __syncthreads();
    {
        const float* other = part + ((half^1)*256 + pidx)*50;
        #pragma unroll
        for (int k = 0; k < 25; k++) { A1[k] += other[k]; A2[k] += other[25+k]; }
    }

    // ---- softmax over 25 neighbors (replicated in both halves) ----
    {
        float m1 = A1[0], m2 = A2[0];
        #pragma unroll
        for (int k = 1; k < 25; k++) { m1 = fmaxf(m1, A1[k]); m2 = fmaxf(m2, A2[k]); }
        float s1 = 0.f, s2 = 0.f;
        #pragma unroll
        for (int k = 0; k < 25; k++) {
            A1[k] = __expf(A1[k] - m1); s1 += A1[k];
            A2[k] = __expf(A2[k] - m2); s2 += A2[k];
        }
        float i1 = 1.f/s1, i2 = 1.f/s2;
        #pragma unroll
        for (int k = 0; k < 25; k++) { A1[k] *= i1; A2[k] *= i2; }
    }
    __syncthreads();   // partial reads done before V overwrites nothing (sep buf) — keeps phases aligned

    // ---- aggregate: 2 chunks x 16 own channels ----
    const float* Vb = V + (size_t)b*CHW;
    float* Ob = O + (size_t)b*CHW + (h0 + r0)*128 + (w0 + wx);
    #pragma unroll
    for (int ck = 0; ck < 2; ck++) {
        load_halo_chunk(Vb + ck*ACH*HW, s, tid, h0, w0);
        __syncthreads();

        const float* base0 = s + (half*16)*NPOS + r0*WC + wx;
        for (int c = 0; c < 16; c++) {
            const float* vs = base0 + c*NPOS;
            float n[6][5];
            #pragma unroll
            for (int j = 0; j < 6; j++)
                #pragma unroll
                for (int i = 0; i < 5; i++)
                    n[j][i] = vs[j*WC + i];
            float o1 = 0.f, o2 = 0.f;
            #pragma unroll
            for (int j = 0; j < 5; j++)
                #pragma unroll
                for (int i = 0; i < 5; i++) {
                    o1 += A1[j*5+i] * n[j][i];
                    o2 += A2[j*5+i] * n[j+1][i];
                }
            int cg = ck*ACH + half*16 + c;
            Ob[(size_t)cg*HW]       = o1;
            Ob[(size_t)cg*HW + 128] = o2;
        }
        __syncthreads();
    }
}

// ---------------------------------------------------------------------------
extern "C" void kernel_launch(void* const* d_in, const int* in_sizes, int n_in,
                              void* d_out, int out_size)
{
    const float* x  = (const float*)d_in[0];
    const float* y  = (const float*)d_in[1];
    const float* wx = (const float*)d_in[2];
    const float* bx = (const float*)d_in[3];
    const float* wy = (const float*)d_in[4];
    const float* by = (const float*)d_in[5];
    const float* wo = (const float*)d_in[6];
    const float* bo = (const float*)d_in[7];
    float* out = (float*)d_out;

    void *pQ, *pV, *pO;
    cudaGetSymbolAddress(&pQ, g_Q);
    cudaGetSymbolAddress(&pV, g_V);
    cudaGetSymbolAddress(&pO, g_O);

    cudaFuncSetAttribute(qv_conv_kernel,  cudaFuncAttributeMaxDynamicSharedMemorySize, CONV_SMEM);
    cudaFuncSetAttribute(out_conv_kernel, cudaFuncAttributeMaxDynamicSharedMemorySize, CONV_SMEM);
    cudaFuncSetAttribute(attn_kernel,     cudaFuncAttributeMaxDynamicSharedMemorySize, ATTN_SMEM);

    // q = wy @ y + by ; v = wx @ x + bx  (one fused launch, gridDim.y selects)
    qv_conv_kernel<<<dim3(NCTA, 2), 256, CONV_SMEM>>>(
        x, y, wx, bx, wy, by, (float*)pQ, (float*)pV);

    // scores + softmax + aggregate (channel-split warp specialization)
    attn_kernel<<<dim3(128/WT, 128/HT, 4), 512, ATTN_SMEM>>>(
        (const float*)pQ, (const float*)pV, (float*)pO);

    // out = wo @ O + bo + x
    out_conv_kernel<<<NCTA, 256, CONV_SMEM>>>((const float*)pO, wo, bo, x, out);
}